// round 11
// baseline (speedup 1.0000x reference)
#include <cuda_runtime.h>
#include <cuda_bf16.h>
#include <math.h>

#define N_NODES 100000
#define N_EDGES 800000
#define D 64
#define D_FEAT 10
#define VOCAB 100
#define EPS 1e-8f

#define NB 148     // persistent CSR blocks
#define BT 256
#define CHUNK 676  // ceil(N_NODES / NB)
#define PAD_CAP 1500032   // >= worst-case padded edge total (800000 + 7*100000)

// packed fp32x2 ops (sm_100+; ptxas only emits via explicit PTX)
#define FMA_F32X2(out, a, b, c) \
    asm("fma.rn.f32x2 %0, %1, %2, %3;" : "=l"(out) : "l"(a), "l"(b), "l"(c))
#define ADD_F32X2(out, a, b) \
    asm("add.rn.f32x2 %0, %1, %2;" : "=l"(out) : "l"(a), "l"(b))

// ---------------- static device scratch ----------------
// z / z2 have one extra, permanently-zero row at index N_NODES (pad sentinel target):
// device globals are zero-initialized and row N_NODES is never written.
__device__ float g_z[(N_NODES + 1) * D];
__device__ float g_h[N_NODES * D];
__device__ float g_z2[(N_NODES + 1) * D];
__device__ int   g_indeg[N_NODES];
__device__ int   g_off[N_NODES + 1];
__device__ int   g_cursor[N_NODES];
__device__ int   g_srcs[PAD_CAP];
__device__ float g_nv[VOCAB * D];
__device__ float g_fw2t[D_FEAT * D];
__device__ float g_c[D];
__device__ unsigned int g_barrier[8];   // zero-init; atomicInc wraps to 0 each replay
__device__ int g_bsum[NB];
__device__ int g_bbase[NB];

// ---------------- grid barrier (self-resetting) ----------------
__device__ __forceinline__ void gbar(int i) {
    __syncthreads();
    if (threadIdx.x == 0) {
        __threadfence();
        atomicInc(&g_barrier[i], NB - 1u);
        volatile unsigned int* p = &g_barrier[i];
        while (*p != 0u) __nanosleep(32);
        __threadfence();
    }
    __syncthreads();
}

// ---------------- CSR build (8-padded) + folded weights + z1 ----------------
#define WP 65
__global__ __launch_bounds__(BT)
void csr_build_kernel(const int2* __restrict__ edges,
                      const float* __restrict__ node_emb,
                      const float* __restrict__ feat_W,
                      const float* __restrict__ feat_b,
                      const float* __restrict__ W,
                      const int* __restrict__ nodes,
                      const float* __restrict__ features) {
    int tid  = threadIdx.x;
    int b    = blockIdx.x;
    int lane = tid & 31;
    int w    = tid >> 5;
    int gt   = b * BT + tid;
    const int gs = NB * BT;

    __shared__ int sm8[8];
    __shared__ float s_fw2t[D_FEAT * D];
    __shared__ float s_c[D];

    // phase 0: blocks 0..25 compute folded weights
    if (b <= 25) {
        __shared__ float sW[D * WP];
        for (int i = tid; i < D * D; i += BT) sW[(i >> 6) * WP + (i & 63)] = W[i];
        if (b == 0) {
            __shared__ float sFW[D * D_FEAT];
            __shared__ float sFB[D];
            for (int i = tid; i < D * D_FEAT; i += BT) sFW[i] = feat_W[i];
            if (tid < D) sFB[tid] = feat_b[tid];
            __syncthreads();
            for (int i = tid; i < D_FEAT * D; i += BT) {
                int k = i / D, d = i % D;
                float s = 0.f;
                #pragma unroll
                for (int j = 0; j < D; j++) s += sW[d * WP + j] * sFW[j * D_FEAT + k];
                g_fw2t[k * D + d] = s;
            }
            if (tid < D) {
                float cb = 0.f;
                #pragma unroll
                for (int j = 0; j < D; j++) cb += sW[tid * WP + j] * sFB[j];
                g_c[tid] = cb;
            }
        } else {
            __shared__ float sE[4][D];
            int v0 = (b - 1) * 4;
            if (tid < 4 * D) sE[tid >> 6][tid & 63] = node_emb[v0 * D + tid];
            __syncthreads();
            int vl = tid >> 6;
            int d  = tid & 63;
            float s = 0.f;
            #pragma unroll
            for (int j = 0; j < D; j++) s += sW[d * WP + j] * sE[vl][j];
            g_nv[(v0 + vl) * D + d] = s;
        }
        __syncthreads();
    }

    // phase 1: zero indeg + pre-fill padded srcs with sentinel
    for (int i = gt; i < N_NODES; i += gs) g_indeg[i] = 0;
    {
        int4 sent; sent.x = N_NODES; sent.y = N_NODES; sent.z = N_NODES; sent.w = N_NODES;
        int4* s4 = (int4*)g_srcs;
        for (int i = gt; i < PAD_CAP / 4; i += gs) s4[i] = sent;
    }
    gbar(0);

    // phase 2a: z1 = nv[nodes] + features @ fw2^T + c
    for (int i = tid; i < D_FEAT * D; i += BT) s_fw2t[i] = g_fw2t[i];
    if (tid < D) s_c[tid] = g_c[tid];
    __syncthreads();
    for (int q = gt; q < N_NODES * 16; q += gs) {
        int node = q >> 4;
        int dq   = (q & 15) * 4;
        int tok  = __ldg(&nodes[node]);
        const float* f = features + node * D_FEAT;
        float fk[D_FEAT];
        #pragma unroll
        for (int k = 0; k < D_FEAT; k++) fk[k] = f[k];

        float4 acc = *(const float4*)&g_nv[tok * D + dq];
        float4 cc  = *(const float4*)&s_c[dq];
        acc.x += cc.x; acc.y += cc.y; acc.z += cc.z; acc.w += cc.w;
        #pragma unroll
        for (int k = 0; k < D_FEAT; k++) {
            float4 w4 = *(const float4*)&s_fw2t[k * D + dq];
            acc.x += fk[k] * w4.x; acc.y += fk[k] * w4.y;
            acc.z += fk[k] * w4.z; acc.w += fk[k] * w4.w;
        }
        *(float4*)&g_z[node * D + dq] = acc;
    }

    // phase 2b: count (2 edges per LDG.128)
    {
        const int4* e4 = (const int4*)edges;
        for (int i = gt; i < N_EDGES / 2; i += gs) {
            int4 p = __ldg(&e4[i]);
            atomicAdd(&g_indeg[p.y], 1);
            atomicAdd(&g_indeg[p.w], 1);
        }
    }
    gbar(1);

    // phase 3: per-block partial sums of PADDED degrees
    int cs = b * CHUNK;
    int ce = min(cs + CHUNK, N_NODES);
    {
        int s = 0;
        for (int i = cs + tid; i < ce; i += BT) s += (g_indeg[i] + 7) & ~7;
        #pragma unroll
        for (int o = 16; o; o >>= 1) s += __shfl_xor_sync(0xFFFFFFFFu, s, o);
        if (lane == 0) sm8[w] = s;
        __syncthreads();
        if (tid == 0) {
            int t = 0;
            #pragma unroll
            for (int k = 0; k < 8; k++) t += sm8[k];
            g_bsum[b] = t;
        }
    }
    gbar(2);

    // phase 4: block 0 scans block sums
    if (b == 0) {
        int x = (tid < NB) ? g_bsum[tid] : 0;
        int incl = x;
        #pragma unroll
        for (int o = 1; o < 32; o <<= 1) {
            int n = __shfl_up_sync(0xFFFFFFFFu, incl, o);
            if (lane >= o) incl += n;
        }
        __syncthreads();
        if (lane == 31) sm8[w] = incl;
        __syncthreads();
        if (w == 0 && lane < 8) {
            int v = sm8[lane];
            #pragma unroll
            for (int o = 1; o < 8; o <<= 1) {
                int n = __shfl_up_sync(0xFFu, v, o);
                if (lane >= o) v += n;
            }
            sm8[lane] = v;
        }
        __syncthreads();
        int excl = incl - x + (w ? sm8[w - 1] : 0);
        if (tid < NB) g_bbase[tid] = excl;
    }
    gbar(3);

    // phase 5: per-block tile scans (padded) -> off, cursor
    {
        int run = g_bbase[b];
        for (int t0 = cs; t0 < cs + CHUNK; t0 += BT) {
            int i = t0 + tid;
            int x = (i < ce) ? ((g_indeg[i] + 7) & ~7) : 0;
            int incl = x;
            #pragma unroll
            for (int o = 1; o < 32; o <<= 1) {
                int n = __shfl_up_sync(0xFFFFFFFFu, incl, o);
                if (lane >= o) incl += n;
            }
            __syncthreads();
            if (lane == 31) sm8[w] = incl;
            __syncthreads();
            if (w == 0 && lane < 8) {
                int v = sm8[lane];
                #pragma unroll
                for (int o = 1; o < 8; o <<= 1) {
                    int n = __shfl_up_sync(0xFFu, v, o);
                    if (lane >= o) v += n;
                }
                sm8[lane] = v;
            }
            __syncthreads();
            int excl = incl - x + (w ? sm8[w - 1] : 0) + run;
            if (i < ce) { g_off[i] = excl; g_cursor[i] = excl; }
            run += sm8[7];
        }
        if (b == NB - 1 && tid == 0) g_off[N_NODES] = run;   // total padded
    }
    gbar(4);

    // phase 6: place (2 edges per LDG.128)
    {
        const int4* e4 = (const int4*)edges;
        for (int i = gt; i < N_EDGES / 2; i += gs) {
            int4 p = __ldg(&e4[i]);
            g_srcs[atomicAdd(&g_cursor[p.y], 1)] = p.x;
            g_srcs[atomicAdd(&g_cursor[p.w], 1)] = p.z;
        }
    }
}

// ---------------- aggregation: half-warp/node, no predication, int4 idx ----------------
__device__ __forceinline__ float4 agg_node4(const float* __restrict__ z,
                                            int node, int sl) {
    ulonglong2 a0 = *(const ulonglong2*)&z[node * D + sl * 4];
    unsigned long long e0 = a0.x, e1 = a0.y, o0 = 0ULL, o1 = 0ULL;
    int s0 = __ldg(&g_off[node]);
    int s1 = __ldg(&g_off[node + 1]);   // padded multiple of 8; pad -> zero row

    for (int j = s0; j < s1; j += 8) {
        int4 i0 = __ldg((const int4*)(g_srcs + j));       // aligned LDG.128
        int4 i1 = __ldg((const int4*)(g_srcs + j + 4));
        ulonglong2 v0 = *(const ulonglong2*)&z[i0.x * D + sl * 4];
        ulonglong2 v1 = *(const ulonglong2*)&z[i0.y * D + sl * 4];
        ulonglong2 v2 = *(const ulonglong2*)&z[i0.z * D + sl * 4];
        ulonglong2 v3 = *(const ulonglong2*)&z[i0.w * D + sl * 4];
        ulonglong2 v4 = *(const ulonglong2*)&z[i1.x * D + sl * 4];
        ulonglong2 v5 = *(const ulonglong2*)&z[i1.y * D + sl * 4];
        ulonglong2 v6 = *(const ulonglong2*)&z[i1.z * D + sl * 4];
        ulonglong2 v7 = *(const ulonglong2*)&z[i1.w * D + sl * 4];
        ADD_F32X2(e0, e0, v0.x);  ADD_F32X2(e1, e1, v0.y);
        ADD_F32X2(o0, o0, v1.x);  ADD_F32X2(o1, o1, v1.y);
        ADD_F32X2(e0, e0, v2.x);  ADD_F32X2(e1, e1, v2.y);
        ADD_F32X2(o0, o0, v3.x);  ADD_F32X2(o1, o1, v3.y);
        ADD_F32X2(e0, e0, v4.x);  ADD_F32X2(e1, e1, v4.y);
        ADD_F32X2(o0, o0, v5.x);  ADD_F32X2(o1, o1, v5.y);
        ADD_F32X2(e0, e0, v6.x);  ADD_F32X2(e1, e1, v6.y);
        ADD_F32X2(o0, o0, v7.x);  ADD_F32X2(o1, o1, v7.y);
    }
    ADD_F32X2(e0, e0, o0);
    ADD_F32X2(e1, e1, o1);
    float4 r;
    asm("mov.b64 {%0, %1}, %2;" : "=f"(r.x), "=f"(r.y) : "l"(e0));
    asm("mov.b64 {%0, %1}, %2;" : "=f"(r.z), "=f"(r.w) : "l"(e1));
    return r;
}

// ---------------- agg + bias + relu ----------------
__global__ __launch_bounds__(256)
void agg_relu_kernel(const float* __restrict__ z, float* __restrict__ h,
                     const float* __restrict__ bvec) {
    int warp = threadIdx.x >> 5;
    int lane = threadIdx.x & 31;
    int node = blockIdx.x * 16 + warp * 2 + (lane >> 4);
    int sl   = lane & 15;

    float4 acc = agg_node4(z, node, sl);
    float4 b4 = *(const float4*)&bvec[sl * 4];
    acc.x = fmaxf(acc.x + b4.x, 0.f);
    acc.y = fmaxf(acc.y + b4.y, 0.f);
    acc.z = fmaxf(acc.z + b4.z, 0.f);
    acc.w = fmaxf(acc.w + b4.w, 0.f);
    *(float4*)&h[node * D + sl * 4] = acc;
}

// ---------------- GEMM: z2 = h @ W^T (2 t-dims per thread, split-K) ----------------
#define GEMM_GRID 592
#define G_TILES (N_NODES / 8)   // 12500 tiles of 8 nodes
__global__ __launch_bounds__(128, 4)
void gemm_kernel(const float* __restrict__ in, float* __restrict__ out,
                 const float* __restrict__ W) {
    __shared__ __align__(16) float xs[8][D];
    __shared__ float ps[8][D];
    int tid = threadIdx.x;
    int t2  = tid & 31;          // output dims t2 and t2+32
    int kh  = (tid >> 5) & 1;    // K half
    int nh  = tid >> 6;          // node half (4 nodes each)

    unsigned long long wa[16], wb[16];
    const unsigned long long* Wa = (const unsigned long long*)(W + t2 * D + kh * 32);
    const unsigned long long* Wb = (const unsigned long long*)(W + (t2 + 32) * D + kh * 32);
    #pragma unroll
    for (int k = 0; k < 16; k++) { wa[k] = Wa[k]; wb[k] = Wb[k]; }

    const float4* src = (const float4*)in;
    int tile = blockIdx.x;
    float4 r0;
    if (tile < G_TILES) r0 = src[tile * 128 + tid];

    for (; tile < G_TILES; tile += GEMM_GRID) {
        ((float4*)xs)[tid] = r0;
        __syncthreads();
        int nt = tile + GEMM_GRID;
        if (nt < G_TILES) r0 = src[nt * 128 + tid];   // prefetch next tile

        unsigned long long acca[4], accb[4];
        #pragma unroll
        for (int n = 0; n < 4; n++) { acca[n] = 0ULL; accb[n] = 0ULL; }

        #pragma unroll
        for (int n = 0; n < 4; n++) {
            const ulonglong2* x = (const ulonglong2*)&xs[nh * 4 + n][kh * 32];
            #pragma unroll
            for (int dp = 0; dp < 8; dp++) {
                ulonglong2 xv = x[dp];                // LDS.128 -> 4 FFMA2
                FMA_F32X2(acca[n], xv.x, wa[2 * dp],     acca[n]);
                FMA_F32X2(accb[n], xv.x, wb[2 * dp],     accb[n]);
                FMA_F32X2(acca[n], xv.y, wa[2 * dp + 1], acca[n]);
                FMA_F32X2(accb[n], xv.y, wb[2 * dp + 1], accb[n]);
            }
        }

        float va[4], vb[4];
        #pragma unroll
        for (int n = 0; n < 4; n++) {
            float lo, hi;
            asm("mov.b64 {%0, %1}, %2;" : "=f"(lo), "=f"(hi) : "l"(acca[n]));
            va[n] = lo + hi;
            asm("mov.b64 {%0, %1}, %2;" : "=f"(lo), "=f"(hi) : "l"(accb[n]));
            vb[n] = lo + hi;
        }

        if (kh == 1) {
            #pragma unroll
            for (int n = 0; n < 4; n++) {
                ps[nh * 4 + n][t2]      = va[n];
                ps[nh * 4 + n][t2 + 32] = vb[n];
            }
        }
        __syncthreads();
        if (kh == 0) {
            int nb = tile * 8 + nh * 4;
            #pragma unroll
            for (int n = 0; n < 4; n++) {
                out[(nb + n) * D + t2]      = va[n] + ps[nh * 4 + n][t2];
                out[(nb + n) * D + t2 + 32] = vb[n] + ps[nh * 4 + n][t2 + 32];
            }
        }
        __syncthreads();
    }
}

// ---------------- fused final: agg + bias + relu + cosine ----------------
__global__ __launch_bounds__(256)
void agg_cos_kernel(const float* __restrict__ z,
                    const float* __restrict__ bvec,
                    const float* __restrict__ pattern_emb,
                    const int* __restrict__ pid,
                    float* __restrict__ out) {
    int warp = threadIdx.x >> 5;
    int lane = threadIdx.x & 31;
    int node = blockIdx.x * 16 + warp * 2 + (lane >> 4);
    int sl   = lane & 15;

    float4 acc = agg_node4(z, node, sl);
    float4 b4 = *(const float4*)&bvec[sl * 4];
    acc.x = fmaxf(acc.x + b4.x, 0.f);
    acc.y = fmaxf(acc.y + b4.y, 0.f);
    acc.z = fmaxf(acc.z + b4.z, 0.f);
    acc.w = fmaxf(acc.w + b4.w, 0.f);

    int p_id = __ldg(pid);
    float4 pv = *(const float4*)&pattern_emb[p_id * D + sl * 4];

    float num = acc.x * pv.x + acc.y * pv.y + acc.z * pv.z + acc.w * pv.w;
    float sq  = acc.x * acc.x + acc.y * acc.y + acc.z * acc.z + acc.w * acc.w;
    float psq = pv.x * pv.x + pv.y * pv.y + pv.z * pv.z + pv.w * pv.w;

    #pragma unroll
    for (int o = 8; o > 0; o >>= 1) {   // reduce within 16-lane half
        num += __shfl_xor_sync(0xFFFFFFFFu, num, o);
        sq  += __shfl_xor_sync(0xFFFFFFFFu, sq, o);
        psq += __shfl_xor_sync(0xFFFFFFFFu, psq, o);
    }
    if (sl == 0) {
        float denom = fmaxf(sqrtf(sq), EPS) * fmaxf(sqrtf(psq), EPS);
        out[node] = num / denom;
    }
}

// ---------------- launch ----------------
extern "C" void kernel_launch(void* const* d_in, const int* in_sizes, int n_in,
                              void* d_out, int out_size) {
    const int*   nodes       = (const int*)d_in[0];
    const int2*  edges       = (const int2*)d_in[1];
    const float* features    = (const float*)d_in[2];
    const float* node_emb    = (const float*)d_in[3];
    const float* feat_W      = (const float*)d_in[4];
    const float* feat_b      = (const float*)d_in[5];
    const float* conv1_W     = (const float*)d_in[6];
    const float* conv1_b     = (const float*)d_in[7];
    const float* pattern_emb = (const float*)d_in[8];
    const int*   pattern_id  = (const int*)d_in[9];
    float*       out         = (float*)d_out;

    float* z; float* h; float* z2;
    cudaGetSymbolAddress((void**)&z,  g_z);
    cudaGetSymbolAddress((void**)&h,  g_h);
    cudaGetSymbolAddress((void**)&z2, g_z2);

    // 1: CSR build (8-padded) + folded weights + z1 (persistent)
    csr_build_kernel<<<NB, BT>>>(edges, node_emb, feat_W, feat_b, conv1_W,
                                 nodes, features);
    // 2: layer-1 agg + relu
    agg_relu_kernel<<<N_NODES / 16, 256>>>(z, h, conv1_b);
    // 3: layer-2 linear
    gemm_kernel<<<GEMM_GRID, 128>>>(h, z2, conv1_W);
    // 4: layer-2 agg + relu + cosine
    agg_cos_kernel<<<N_NODES / 16, 256>>>(z2, conv1_b, pattern_emb, pattern_id, out);
}

// round 12
// speedup vs baseline: 1.0145x; 1.0145x over previous
#include <cuda_runtime.h>
#include <cuda_bf16.h>
#include <math.h>

#define N_NODES 100000
#define N_EDGES 800000
#define D 64
#define D_FEAT 10
#define VOCAB 100
#define EPS 1e-8f

#define NB 148     // persistent CSR blocks
#define BT 256
#define CHUNK 676  // ceil(N_NODES / NB)

// packed fp32x2 ops (sm_100+; ptxas only emits via explicit PTX)
#define FMA_F32X2(out, a, b, c) \
    asm("fma.rn.f32x2 %0, %1, %2, %3;" : "=l"(out) : "l"(a), "l"(b), "l"(c))
#define ADD_F32X2(out, a, b) \
    asm("add.rn.f32x2 %0, %1, %2;" : "=l"(out) : "l"(a), "l"(b))

// ---------------- static device scratch ----------------
__device__ float g_z[N_NODES * D];
__device__ float g_h[N_NODES * D];
__device__ float g_z2[N_NODES * D];
__device__ int   g_indeg[N_NODES];
__device__ int   g_off[N_NODES + 1];
__device__ int   g_cursor[N_NODES];
__device__ int   g_srcs[N_EDGES];      // stores BYTE offsets (src * 256)
__device__ float g_nv[VOCAB * D];
__device__ float g_fw2t[D_FEAT * D];
__device__ float g_c[D];
__device__ unsigned int g_barrier[8];  // zero-init; atomicInc wraps to 0 each replay
__device__ int g_bsum[NB];
__device__ int g_bbase[NB];

// ---------------- grid barrier (self-resetting) ----------------
__device__ __forceinline__ void gbar(int i) {
    __syncthreads();
    if (threadIdx.x == 0) {
        __threadfence();
        atomicInc(&g_barrier[i], NB - 1u);
        volatile unsigned int* p = &g_barrier[i];
        while (*p != 0u) __nanosleep(32);
        __threadfence();
    }
    __syncthreads();
}

// ---------------- CSR build + folded weights + z1 (one persistent kernel) ----------------
#define WP 65
__global__ __launch_bounds__(BT)
void csr_build_kernel(const int2* __restrict__ edges,
                      const float* __restrict__ node_emb,
                      const float* __restrict__ feat_W,
                      const float* __restrict__ feat_b,
                      const float* __restrict__ W,
                      const int* __restrict__ nodes,
                      const float* __restrict__ features) {
    int tid  = threadIdx.x;
    int b    = blockIdx.x;
    int lane = tid & 31;
    int w    = tid >> 5;
    int gt   = b * BT + tid;
    const int gs = NB * BT;

    __shared__ int sm8[8];
    __shared__ float s_fw2t[D_FEAT * D];
    __shared__ float s_c[D];

    // phase 0: blocks 0..25 compute folded weights
    if (b <= 25) {
        __shared__ float sW[D * WP];
        for (int i = tid; i < D * D; i += BT) sW[(i >> 6) * WP + (i & 63)] = W[i];
        if (b == 0) {
            __shared__ float sFW[D * D_FEAT];
            __shared__ float sFB[D];
            for (int i = tid; i < D * D_FEAT; i += BT) sFW[i] = feat_W[i];
            if (tid < D) sFB[tid] = feat_b[tid];
            __syncthreads();
            for (int i = tid; i < D_FEAT * D; i += BT) {
                int k = i / D, d = i % D;
                float s = 0.f;
                #pragma unroll
                for (int j = 0; j < D; j++) s += sW[d * WP + j] * sFW[j * D_FEAT + k];
                g_fw2t[k * D + d] = s;
            }
            if (tid < D) {
                float cb = 0.f;
                #pragma unroll
                for (int j = 0; j < D; j++) cb += sW[tid * WP + j] * sFB[j];
                g_c[tid] = cb;
            }
        } else {
            __shared__ float sE[4][D];
            int v0 = (b - 1) * 4;
            if (tid < 4 * D) sE[tid >> 6][tid & 63] = node_emb[v0 * D + tid];
            __syncthreads();
            int vl = tid >> 6;
            int d  = tid & 63;
            float s = 0.f;
            #pragma unroll
            for (int j = 0; j < D; j++) s += sW[d * WP + j] * sE[vl][j];
            g_nv[(v0 + vl) * D + d] = s;
        }
        __syncthreads();
    }

    // phase 1: zero indeg
    for (int i = gt; i < N_NODES; i += gs) g_indeg[i] = 0;
    gbar(0);

    // phase 2a: z1 = nv[nodes] + features @ fw2^T + c
    for (int i = tid; i < D_FEAT * D; i += BT) s_fw2t[i] = g_fw2t[i];
    if (tid < D) s_c[tid] = g_c[tid];
    __syncthreads();
    for (int q = gt; q < N_NODES * 16; q += gs) {
        int node = q >> 4;
        int dq   = (q & 15) * 4;
        int tok  = __ldg(&nodes[node]);
        const float* f = features + node * D_FEAT;
        float fk[D_FEAT];
        #pragma unroll
        for (int k = 0; k < D_FEAT; k++) fk[k] = f[k];

        float4 acc = *(const float4*)&g_nv[tok * D + dq];
        float4 cc  = *(const float4*)&s_c[dq];
        acc.x += cc.x; acc.y += cc.y; acc.z += cc.z; acc.w += cc.w;
        #pragma unroll
        for (int k = 0; k < D_FEAT; k++) {
            float4 w4 = *(const float4*)&s_fw2t[k * D + dq];
            acc.x += fk[k] * w4.x; acc.y += fk[k] * w4.y;
            acc.z += fk[k] * w4.z; acc.w += fk[k] * w4.w;
        }
        *(float4*)&g_z[node * D + dq] = acc;
    }

    // phase 2b: count (2 edges per LDG.128)
    {
        const int4* e4 = (const int4*)edges;
        for (int i = gt; i < N_EDGES / 2; i += gs) {
            int4 p = __ldg(&e4[i]);
            atomicAdd(&g_indeg[p.y], 1);
            atomicAdd(&g_indeg[p.w], 1);
        }
    }
    gbar(1);

    // phase 3: per-block partial sums
    int cs = b * CHUNK;
    int ce = min(cs + CHUNK, N_NODES);
    {
        int s = 0;
        for (int i = cs + tid; i < ce; i += BT) s += g_indeg[i];
        #pragma unroll
        for (int o = 16; o; o >>= 1) s += __shfl_xor_sync(0xFFFFFFFFu, s, o);
        if (lane == 0) sm8[w] = s;
        __syncthreads();
        if (tid == 0) {
            int t = 0;
            #pragma unroll
            for (int k = 0; k < 8; k++) t += sm8[k];
            g_bsum[b] = t;
        }
    }
    gbar(2);

    // phase 4: block 0 scans block sums
    if (b == 0) {
        int x = (tid < NB) ? g_bsum[tid] : 0;
        int incl = x;
        #pragma unroll
        for (int o = 1; o < 32; o <<= 1) {
            int n = __shfl_up_sync(0xFFFFFFFFu, incl, o);
            if (lane >= o) incl += n;
        }
        __syncthreads();
        if (lane == 31) sm8[w] = incl;
        __syncthreads();
        if (w == 0 && lane < 8) {
            int v = sm8[lane];
            #pragma unroll
            for (int o = 1; o < 8; o <<= 1) {
                int n = __shfl_up_sync(0xFFu, v, o);
                if (lane >= o) v += n;
            }
            sm8[lane] = v;
        }
        __syncthreads();
        int excl = incl - x + (w ? sm8[w - 1] : 0);
        if (tid < NB) g_bbase[tid] = excl;
    }
    gbar(3);

    // phase 5: per-block tile scans -> off, cursor
    {
        int run = g_bbase[b];
        for (int t0 = cs; t0 < cs + CHUNK; t0 += BT) {
            int i = t0 + tid;
            int x = (i < ce) ? g_indeg[i] : 0;
            int incl = x;
            #pragma unroll
            for (int o = 1; o < 32; o <<= 1) {
                int n = __shfl_up_sync(0xFFFFFFFFu, incl, o);
                if (lane >= o) incl += n;
            }
            __syncthreads();
            if (lane == 31) sm8[w] = incl;
            __syncthreads();
            if (w == 0 && lane < 8) {
                int v = sm8[lane];
                #pragma unroll
                for (int o = 1; o < 8; o <<= 1) {
                    int n = __shfl_up_sync(0xFFu, v, o);
                    if (lane >= o) v += n;
                }
                sm8[lane] = v;
            }
            __syncthreads();
            int excl = incl - x + (w ? sm8[w - 1] : 0) + run;
            if (i < ce) { g_off[i] = excl; g_cursor[i] = excl; }
            run += sm8[7];
        }
        if (b == 0 && tid == 0) g_off[N_NODES] = N_EDGES;
    }
    gbar(4);

    // phase 6: place (2 edges per LDG.128); store BYTE offsets (src * 256)
    {
        const int4* e4 = (const int4*)edges;
        for (int i = gt; i < N_EDGES / 2; i += gs) {
            int4 p = __ldg(&e4[i]);
            g_srcs[atomicAdd(&g_cursor[p.y], 1)] = p.x << 8;
            g_srcs[atomicAdd(&g_cursor[p.w], 1)] = p.z << 8;
        }
    }
}

// ---------------- aggregation: half-warp/node, byte-offset srcs, main8 + tail ----------------
__device__ __forceinline__ float4 agg_node4(const float* __restrict__ z,
                                            int node, int sl) {
    const char* zb = (const char*)z + sl * 16;     // per-lane base
    ulonglong2 a0 = *(const ulonglong2*)(zb + node * 256);
    unsigned long long e0 = a0.x, e1 = a0.y, o0 = 0ULL, o1 = 0ULL;
    int s0 = __ldg(&g_off[node]);
    int s1 = __ldg(&g_off[node + 1]);
    int n8 = s0 + ((s1 - s0) & ~7);

    for (int j = s0; j < n8; j += 8) {             // unpredicated main loop
        int f0 = __ldg(&g_srcs[j + 0]);
        int f1 = __ldg(&g_srcs[j + 1]);
        int f2 = __ldg(&g_srcs[j + 2]);
        int f3 = __ldg(&g_srcs[j + 3]);
        int f4 = __ldg(&g_srcs[j + 4]);
        int f5 = __ldg(&g_srcs[j + 5]);
        int f6 = __ldg(&g_srcs[j + 6]);
        int f7 = __ldg(&g_srcs[j + 7]);
        ulonglong2 v0 = *(const ulonglong2*)(zb + f0);
        ulonglong2 v1 = *(const ulonglong2*)(zb + f1);
        ulonglong2 v2 = *(const ulonglong2*)(zb + f2);
        ulonglong2 v3 = *(const ulonglong2*)(zb + f3);
        ulonglong2 v4 = *(const ulonglong2*)(zb + f4);
        ulonglong2 v5 = *(const ulonglong2*)(zb + f5);
        ulonglong2 v6 = *(const ulonglong2*)(zb + f6);
        ulonglong2 v7 = *(const ulonglong2*)(zb + f7);
        ADD_F32X2(e0, e0, v0.x);  ADD_F32X2(e1, e1, v0.y);
        ADD_F32X2(o0, o0, v1.x);  ADD_F32X2(o1, o1, v1.y);
        ADD_F32X2(e0, e0, v2.x);  ADD_F32X2(e1, e1, v2.y);
        ADD_F32X2(o0, o0, v3.x);  ADD_F32X2(o1, o1, v3.y);
        ADD_F32X2(e0, e0, v4.x);  ADD_F32X2(e1, e1, v4.y);
        ADD_F32X2(o0, o0, v5.x);  ADD_F32X2(o1, o1, v5.y);
        ADD_F32X2(e0, e0, v6.x);  ADD_F32X2(e1, e1, v6.y);
        ADD_F32X2(o0, o0, v7.x);  ADD_F32X2(o1, o1, v7.y);
    }
    for (int j = n8; j < s1; j++) {                // short tail (avg ~3.5)
        int f = __ldg(&g_srcs[j]);
        ulonglong2 v = *(const ulonglong2*)(zb + f);
        ADD_F32X2(e0, e0, v.x);
        ADD_F32X2(e1, e1, v.y);
    }
    ADD_F32X2(e0, e0, o0);
    ADD_F32X2(e1, e1, o1);
    float4 r;
    asm("mov.b64 {%0, %1}, %2;" : "=f"(r.x), "=f"(r.y) : "l"(e0));
    asm("mov.b64 {%0, %1}, %2;" : "=f"(r.z), "=f"(r.w) : "l"(e1));
    return r;
}

// ---------------- agg + bias + relu ----------------
__global__ __launch_bounds__(256)
void agg_relu_kernel(const float* __restrict__ z, float* __restrict__ h,
                     const float* __restrict__ bvec) {
    int warp = threadIdx.x >> 5;
    int lane = threadIdx.x & 31;
    int node = blockIdx.x * 16 + warp * 2 + (lane >> 4);
    int sl   = lane & 15;

    float4 acc = agg_node4(z, node, sl);
    float4 b4 = *(const float4*)&bvec[sl * 4];
    acc.x = fmaxf(acc.x + b4.x, 0.f);
    acc.y = fmaxf(acc.y + b4.y, 0.f);
    acc.z = fmaxf(acc.z + b4.z, 0.f);
    acc.w = fmaxf(acc.w + b4.w, 0.f);
    *(float4*)&h[node * D + sl * 4] = acc;
}

// ---------------- GEMM: z2 = h @ W^T (2 t-dims per thread, split-K) ----------------
#define GEMM_GRID 592
#define G_TILES (N_NODES / 8)   // 12500 tiles of 8 nodes
__global__ __launch_bounds__(128, 4)
void gemm_kernel(const float* __restrict__ in, float* __restrict__ out,
                 const float* __restrict__ W) {
    __shared__ __align__(16) float xs[8][D];
    __shared__ float ps[8][D];
    int tid = threadIdx.x;
    int t2  = tid & 31;          // output dims t2 and t2+32
    int kh  = (tid >> 5) & 1;    // K half
    int nh  = tid >> 6;          // node half (4 nodes each)

    unsigned long long wa[16], wb[16];
    const unsigned long long* Wa = (const unsigned long long*)(W + t2 * D + kh * 32);
    const unsigned long long* Wb = (const unsigned long long*)(W + (t2 + 32) * D + kh * 32);
    #pragma unroll
    for (int k = 0; k < 16; k++) { wa[k] = Wa[k]; wb[k] = Wb[k]; }

    const float4* src = (const float4*)in;
    int tile = blockIdx.x;
    float4 r0;
    if (tile < G_TILES) r0 = src[tile * 128 + tid];

    for (; tile < G_TILES; tile += GEMM_GRID) {
        ((float4*)xs)[tid] = r0;
        __syncthreads();
        int nt = tile + GEMM_GRID;
        if (nt < G_TILES) r0 = src[nt * 128 + tid];   // prefetch next tile

        unsigned long long acca[4], accb[4];
        #pragma unroll
        for (int n = 0; n < 4; n++) { acca[n] = 0ULL; accb[n] = 0ULL; }

        #pragma unroll
        for (int n = 0; n < 4; n++) {
            const ulonglong2* x = (const ulonglong2*)&xs[nh * 4 + n][kh * 32];
            #pragma unroll
            for (int dp = 0; dp < 8; dp++) {
                ulonglong2 xv = x[dp];                // LDS.128 -> 4 FFMA2
                FMA_F32X2(acca[n], xv.x, wa[2 * dp],     acca[n]);
                FMA_F32X2(accb[n], xv.x, wb[2 * dp],     accb[n]);
                FMA_F32X2(acca[n], xv.y, wa[2 * dp + 1], acca[n]);
                FMA_F32X2(accb[n], xv.y, wb[2 * dp + 1], accb[n]);
            }
        }

        float va[4], vb[4];
        #pragma unroll
        for (int n = 0; n < 4; n++) {
            float lo, hi;
            asm("mov.b64 {%0, %1}, %2;" : "=f"(lo), "=f"(hi) : "l"(acca[n]));
            va[n] = lo + hi;
            asm("mov.b64 {%0, %1}, %2;" : "=f"(lo), "=f"(hi) : "l"(accb[n]));
            vb[n] = lo + hi;
        }

        if (kh == 1) {
            #pragma unroll
            for (int n = 0; n < 4; n++) {
                ps[nh * 4 + n][t2]      = va[n];
                ps[nh * 4 + n][t2 + 32] = vb[n];
            }
        }
        __syncthreads();
        if (kh == 0) {
            int nb = tile * 8 + nh * 4;
            #pragma unroll
            for (int n = 0; n < 4; n++) {
                out[(nb + n) * D + t2]      = va[n] + ps[nh * 4 + n][t2];
                out[(nb + n) * D + t2 + 32] = vb[n] + ps[nh * 4 + n][t2 + 32];
            }
        }
        __syncthreads();
    }
}

// ---------------- fused final: agg + bias + relu + cosine ----------------
__global__ __launch_bounds__(256)
void agg_cos_kernel(const float* __restrict__ z,
                    const float* __restrict__ bvec,
                    const float* __restrict__ pattern_emb,
                    const int* __restrict__ pid,
                    float* __restrict__ out) {
    int warp = threadIdx.x >> 5;
    int lane = threadIdx.x & 31;
    int node = blockIdx.x * 16 + warp * 2 + (lane >> 4);
    int sl   = lane & 15;

    float4 acc = agg_node4(z, node, sl);
    float4 b4 = *(const float4*)&bvec[sl * 4];
    acc.x = fmaxf(acc.x + b4.x, 0.f);
    acc.y = fmaxf(acc.y + b4.y, 0.f);
    acc.z = fmaxf(acc.z + b4.z, 0.f);
    acc.w = fmaxf(acc.w + b4.w, 0.f);

    int p_id = __ldg(pid);
    float4 pv = *(const float4*)&pattern_emb[p_id * D + sl * 4];

    float num = acc.x * pv.x + acc.y * pv.y + acc.z * pv.z + acc.w * pv.w;
    float sq  = acc.x * acc.x + acc.y * acc.y + acc.z * acc.z + acc.w * acc.w;
    float psq = pv.x * pv.x + pv.y * pv.y + pv.z * pv.z + pv.w * pv.w;

    #pragma unroll
    for (int o = 8; o > 0; o >>= 1) {   // reduce within 16-lane half
        num += __shfl_xor_sync(0xFFFFFFFFu, num, o);
        sq  += __shfl_xor_sync(0xFFFFFFFFu, sq, o);
        psq += __shfl_xor_sync(0xFFFFFFFFu, psq, o);
    }
    if (sl == 0) {
        float denom = fmaxf(sqrtf(sq), EPS) * fmaxf(sqrtf(psq), EPS);
        out[node] = num / denom;
    }
}

// ---------------- launch ----------------
extern "C" void kernel_launch(void* const* d_in, const int* in_sizes, int n_in,
                              void* d_out, int out_size) {
    const int*   nodes       = (const int*)d_in[0];
    const int2*  edges       = (const int2*)d_in[1];
    const float* features    = (const float*)d_in[2];
    const float* node_emb    = (const float*)d_in[3];
    const float* feat_W      = (const float*)d_in[4];
    const float* feat_b      = (const float*)d_in[5];
    const float* conv1_W     = (const float*)d_in[6];
    const float* conv1_b     = (const float*)d_in[7];
    const float* pattern_emb = (const float*)d_in[8];
    const int*   pattern_id  = (const int*)d_in[9];
    float*       out         = (float*)d_out;

    float* z; float* h; float* z2;
    cudaGetSymbolAddress((void**)&z,  g_z);
    cudaGetSymbolAddress((void**)&h,  g_h);
    cudaGetSymbolAddress((void**)&z2, g_z2);

    // 1: CSR build + folded weights + z1 (persistent)
    csr_build_kernel<<<NB, BT>>>(edges, node_emb, feat_W, feat_b, conv1_W,
                                 nodes, features);
    // 2: layer-1 agg + relu
    agg_relu_kernel<<<N_NODES / 16, 256>>>(z, h, conv1_b);
    // 3: layer-2 linear
    gemm_kernel<<<GEMM_GRID, 128>>>(h, z2, conv1_W);
    // 4: layer-2 agg + relu + cosine
    agg_cos_kernel<<<N_NODES / 16, 256>>>(z2, conv1_b, pattern_emb, pattern_id, out);
}

// round 14
// speedup vs baseline: 1.0452x; 1.0302x over previous
#include <cuda_runtime.h>
#include <cuda_bf16.h>
#include <math.h>

#define N_NODES 100000
#define N_EDGES 800000
#define D 64
#define D_FEAT 10
#define VOCAB 100
#define EPS 1e-8f

#define NB 148     // persistent CSR blocks
#define BT 256
#define CHUNK 676  // ceil(N_NODES / NB)

// packed fp32x2 ops (sm_100+; ptxas only emits via explicit PTX)
#define FMA_F32X2(out, a, b, c) \
    asm("fma.rn.f32x2 %0, %1, %2, %3;" : "=l"(out) : "l"(a), "l"(b), "l"(c))
#define ADD_F32X2(out, a, b) \
    asm("add.rn.f32x2 %0, %1, %2;" : "=l"(out) : "l"(a), "l"(b))

// ---------------- static device scratch ----------------
__device__ float g_z[N_NODES * D];
__device__ float g_h[N_NODES * D];
__device__ float g_z2[N_NODES * D];
__device__ int   g_indeg[N_NODES];
__device__ int   g_off[N_NODES + 1];
__device__ int   g_cursor[N_NODES];
__device__ int   g_srcs[N_EDGES];      // stores BYTE offsets (src * 256)
__device__ float g_nv[VOCAB * D];
__device__ float g_fw2t[D_FEAT * D];
__device__ float g_c[D];
__device__ unsigned int g_barrier[8];  // zero-init; atomicInc wraps to 0 each replay
__device__ int g_bsum[NB];
__device__ int g_bbase[NB];

// ---------------- grid barrier (self-resetting) ----------------
__device__ __forceinline__ void gbar(int i) {
    __syncthreads();
    if (threadIdx.x == 0) {
        __threadfence();
        atomicInc(&g_barrier[i], NB - 1u);
        volatile unsigned int* p = &g_barrier[i];
        while (*p != 0u) __nanosleep(32);
        __threadfence();
    }
    __syncthreads();
}

// ---------------- CSR build + folded weights + z1 (one persistent kernel) ----------------
#define WP 65
__global__ __launch_bounds__(BT)
void csr_build_kernel(const int2* __restrict__ edges,
                      const float* __restrict__ node_emb,
                      const float* __restrict__ feat_W,
                      const float* __restrict__ feat_b,
                      const float* __restrict__ W,
                      const int* __restrict__ nodes,
                      const float* __restrict__ features) {
    int tid  = threadIdx.x;
    int b    = blockIdx.x;
    int lane = tid & 31;
    int w    = tid >> 5;
    int gt   = b * BT + tid;
    const int gs = NB * BT;

    __shared__ int sm8[8];
    __shared__ float s_fw2t[D_FEAT * D];
    __shared__ float s_c[D];

    // phase 0: blocks 0..25 compute folded weights
    if (b <= 25) {
        __shared__ float sW[D * WP];
        for (int i = tid; i < D * D; i += BT) sW[(i >> 6) * WP + (i & 63)] = W[i];
        if (b == 0) {
            __shared__ float sFW[D * D_FEAT];
            __shared__ float sFB[D];
            for (int i = tid; i < D * D_FEAT; i += BT) sFW[i] = feat_W[i];
            if (tid < D) sFB[tid] = feat_b[tid];
            __syncthreads();
            for (int i = tid; i < D_FEAT * D; i += BT) {
                int k = i / D, d = i % D;
                float s = 0.f;
                #pragma unroll
                for (int j = 0; j < D; j++) s += sW[d * WP + j] * sFW[j * D_FEAT + k];
                g_fw2t[k * D + d] = s;
            }
            if (tid < D) {
                float cb = 0.f;
                #pragma unroll
                for (int j = 0; j < D; j++) cb += sW[tid * WP + j] * sFB[j];
                g_c[tid] = cb;
            }
        } else {
            __shared__ float sE[4][D];
            int v0 = (b - 1) * 4;
            if (tid < 4 * D) sE[tid >> 6][tid & 63] = node_emb[v0 * D + tid];
            __syncthreads();
            int vl = tid >> 6;
            int d  = tid & 63;
            float s = 0.f;
            #pragma unroll
            for (int j = 0; j < D; j++) s += sW[d * WP + j] * sE[vl][j];
            g_nv[(v0 + vl) * D + d] = s;
        }
        __syncthreads();
    }

    // phase 1: zero indeg
    for (int i = gt; i < N_NODES; i += gs) g_indeg[i] = 0;
    gbar(0);

    // phase 2a: z1 = nv[nodes] + features @ fw2^T + c
    for (int i = tid; i < D_FEAT * D; i += BT) s_fw2t[i] = g_fw2t[i];
    if (tid < D) s_c[tid] = g_c[tid];
    __syncthreads();
    for (int q = gt; q < N_NODES * 16; q += gs) {
        int node = q >> 4;
        int dq   = (q & 15) * 4;
        int tok  = __ldg(&nodes[node]);
        const float* f = features + node * D_FEAT;
        float fk[D_FEAT];
        #pragma unroll
        for (int k = 0; k < D_FEAT; k++) fk[k] = f[k];

        float4 acc = *(const float4*)&g_nv[tok * D + dq];
        float4 cc  = *(const float4*)&s_c[dq];
        acc.x += cc.x; acc.y += cc.y; acc.z += cc.z; acc.w += cc.w;
        #pragma unroll
        for (int k = 0; k < D_FEAT; k++) {
            float4 w4 = *(const float4*)&s_fw2t[k * D + dq];
            acc.x += fk[k] * w4.x; acc.y += fk[k] * w4.y;
            acc.z += fk[k] * w4.z; acc.w += fk[k] * w4.w;
        }
        *(float4*)&g_z[node * D + dq] = acc;
    }

    // phase 2b: count (2 edges per LDG.128)
    {
        const int4* e4 = (const int4*)edges;
        for (int i = gt; i < N_EDGES / 2; i += gs) {
            int4 p = __ldg(&e4[i]);
            atomicAdd(&g_indeg[p.y], 1);
            atomicAdd(&g_indeg[p.w], 1);
        }
    }
    gbar(1);

    // phase 3: per-block partial sums
    int cs = b * CHUNK;
    int ce = min(cs + CHUNK, N_NODES);
    {
        int s = 0;
        for (int i = cs + tid; i < ce; i += BT) s += g_indeg[i];
        #pragma unroll
        for (int o = 16; o; o >>= 1) s += __shfl_xor_sync(0xFFFFFFFFu, s, o);
        if (lane == 0) sm8[w] = s;
        __syncthreads();
        if (tid == 0) {
            int t = 0;
            #pragma unroll
            for (int k = 0; k < 8; k++) t += sm8[k];
            g_bsum[b] = t;
        }
    }
    gbar(2);

    // phase 4: block 0 scans block sums (deterministic, globally monotone)
    if (b == 0) {
        int x = (tid < NB) ? g_bsum[tid] : 0;
        int incl = x;
        #pragma unroll
        for (int o = 1; o < 32; o <<= 1) {
            int n = __shfl_up_sync(0xFFFFFFFFu, incl, o);
            if (lane >= o) incl += n;
        }
        __syncthreads();
        if (lane == 31) sm8[w] = incl;
        __syncthreads();
        if (w == 0 && lane < 8) {
            int v = sm8[lane];
            #pragma unroll
            for (int o = 1; o < 8; o <<= 1) {
                int n = __shfl_up_sync(0xFFu, v, o);
                if (lane >= o) v += n;
            }
            sm8[lane] = v;
        }
        __syncthreads();
        int excl = incl - x + (w ? sm8[w - 1] : 0);
        if (tid < NB) g_bbase[tid] = excl;
    }
    gbar(3);

    // phase 5: per-block tile scans -> off, cursor
    {
        int run = g_bbase[b];
        for (int t0 = cs; t0 < cs + CHUNK; t0 += BT) {
            int i = t0 + tid;
            int x = (i < ce) ? g_indeg[i] : 0;
            int incl = x;
            #pragma unroll
            for (int o = 1; o < 32; o <<= 1) {
                int n = __shfl_up_sync(0xFFFFFFFFu, incl, o);
                if (lane >= o) incl += n;
            }
            __syncthreads();
            if (lane == 31) sm8[w] = incl;
            __syncthreads();
            if (w == 0 && lane < 8) {
                int v = sm8[lane];
                #pragma unroll
                for (int o = 1; o < 8; o <<= 1) {
                    int n = __shfl_up_sync(0xFFu, v, o);
                    if (lane >= o) v += n;
                }
                sm8[lane] = v;
            }
            __syncthreads();
            int excl = incl - x + (w ? sm8[w - 1] : 0) + run;
            if (i < ce) { g_off[i] = excl; g_cursor[i] = excl; }
            run += sm8[7];
        }
        if (b == 0 && tid == 0) g_off[N_NODES] = N_EDGES;
    }
    gbar(4);

    // phase 6: place (2 edges per LDG.128); store BYTE offsets (src * 256)
    {
        const int4* e4 = (const int4*)edges;
        for (int i = gt; i < N_EDGES / 2; i += gs) {
            int4 p = __ldg(&e4[i]);
            g_srcs[atomicAdd(&g_cursor[p.y], 1)] = p.x << 8;
            g_srcs[atomicAdd(&g_cursor[p.w], 1)] = p.z << 8;
        }
    }
}

// ---------------- aggregation: half-warp per node, predicated MLP-8, byte offsets ----------------
__device__ __forceinline__ float4 agg_node4(const float* __restrict__ z,
                                            int node, int sl) {
    const char* zb = (const char*)z + sl * 16;     // per-lane base
    ulonglong2 a0 = *(const ulonglong2*)(zb + node * 256);
    unsigned long long e0 = a0.x, e1 = a0.y, o0 = 0ULL, o1 = 0ULL;
    int s0 = __ldg(&g_off[node]);
    int s1 = __ldg(&g_off[node + 1]);

    for (int j = s0; j < s1; j += 8) {
        ulonglong2 v[8];
        #pragma unroll
        for (int k = 0; k < 8; k++) {
            if (j + k < s1) {
                int a = __ldg(&g_srcs[j + k]);   // byte offset; uniform in half-warp
                v[k] = *(const ulonglong2*)(zb + a);
            } else {
                v[k].x = 0ULL; v[k].y = 0ULL;
            }
        }
        #pragma unroll
        for (int k = 0; k < 8; k += 2) {
            ADD_F32X2(e0, e0, v[k].x);     ADD_F32X2(e1, e1, v[k].y);
            ADD_F32X2(o0, o0, v[k + 1].x); ADD_F32X2(o1, o1, v[k + 1].y);
        }
    }
    ADD_F32X2(e0, e0, o0);
    ADD_F32X2(e1, e1, o1);
    float4 r;
    asm("mov.b64 {%0, %1}, %2;" : "=f"(r.x), "=f"(r.y) : "l"(e0));
    asm("mov.b64 {%0, %1}, %2;" : "=f"(r.z), "=f"(r.w) : "l"(e1));
    return r;
}

// ---------------- agg + bias + relu ----------------
__global__ __launch_bounds__(256)
void agg_relu_kernel(const float* __restrict__ z, float* __restrict__ h,
                     const float* __restrict__ bvec) {
    int warp = threadIdx.x >> 5;
    int lane = threadIdx.x & 31;
    int node = blockIdx.x * 16 + warp * 2 + (lane >> 4);
    int sl   = lane & 15;

    float4 acc = agg_node4(z, node, sl);
    float4 b4 = *(const float4*)&bvec[sl * 4];
    acc.x = fmaxf(acc.x + b4.x, 0.f);
    acc.y = fmaxf(acc.y + b4.y, 0.f);
    acc.z = fmaxf(acc.z + b4.z, 0.f);
    acc.w = fmaxf(acc.w + b4.w, 0.f);
    *(float4*)&h[node * D + sl * 4] = acc;
}

// ---------------- GEMM: z2 = h @ W^T (2 t-dims per thread, split-K) ----------------
#define GEMM_GRID 592
#define G_TILES (N_NODES / 8)   // 12500 tiles of 8 nodes
__global__ __launch_bounds__(128, 4)
void gemm_kernel(const float* __restrict__ in, float* __restrict__ out,
                 const float* __restrict__ W) {
    __shared__ __align__(16) float xs[8][D];
    __shared__ float ps[8][D];
    int tid = threadIdx.x;
    int t2  = tid & 31;          // output dims t2 and t2+32
    int kh  = (tid >> 5) & 1;    // K half
    int nh  = tid >> 6;          // node half (4 nodes each)

    unsigned long long wa[16], wb[16];
    const unsigned long long* Wa = (const unsigned long long*)(W + t2 * D + kh * 32);
    const unsigned long long* Wb = (const unsigned long long*)(W + (t2 + 32) * D + kh * 32);
    #pragma unroll
    for (int k = 0; k < 16; k++) { wa[k] = Wa[k]; wb[k] = Wb[k]; }

    const float4* src = (const float4*)in;
    int tile = blockIdx.x;
    float4 r0;
    if (tile < G_TILES) r0 = src[tile * 128 + tid];

    for (; tile < G_TILES; tile += GEMM_GRID) {
        ((float4*)xs)[tid] = r0;
        __syncthreads();
        int nt = tile + GEMM_GRID;
        if (nt < G_TILES) r0 = src[nt * 128 + tid];   // prefetch next tile

        unsigned long long acca[4], accb[4];
        #pragma unroll
        for (int n = 0; n < 4; n++) { acca[n] = 0ULL; accb[n] = 0ULL; }

        #pragma unroll
        for (int n = 0; n < 4; n++) {
            const ulonglong2* x = (const ulonglong2*)&xs[nh * 4 + n][kh * 32];
            #pragma unroll
            for (int dp = 0; dp < 8; dp++) {
                ulonglong2 xv = x[dp];                // LDS.128 -> 4 FFMA2
                FMA_F32X2(acca[n], xv.x, wa[2 * dp],     acca[n]);
                FMA_F32X2(accb[n], xv.x, wb[2 * dp],     accb[n]);
                FMA_F32X2(acca[n], xv.y, wa[2 * dp + 1], acca[n]);
                FMA_F32X2(accb[n], xv.y, wb[2 * dp + 1], accb[n]);
            }
        }

        float va[4], vb[4];
        #pragma unroll
        for (int n = 0; n < 4; n++) {
            float lo, hi;
            asm("mov.b64 {%0, %1}, %2;" : "=f"(lo), "=f"(hi) : "l"(acca[n]));
            va[n] = lo + hi;
            asm("mov.b64 {%0, %1}, %2;" : "=f"(lo), "=f"(hi) : "l"(accb[n]));
            vb[n] = lo + hi;
        }

        if (kh == 1) {
            #pragma unroll
            for (int n = 0; n < 4; n++) {
                ps[nh * 4 + n][t2]      = va[n];
                ps[nh * 4 + n][t2 + 32] = vb[n];
            }
        }
        __syncthreads();
        if (kh == 0) {
            int nb = tile * 8 + nh * 4;
            #pragma unroll
            for (int n = 0; n < 4; n++) {
                out[(nb + n) * D + t2]      = va[n] + ps[nh * 4 + n][t2];
                out[(nb + n) * D + t2 + 32] = vb[n] + ps[nh * 4 + n][t2 + 32];
            }
        }
        __syncthreads();
    }
}

// ---------------- fused final: agg + bias + relu + cosine ----------------
__global__ __launch_bounds__(256)
void agg_cos_kernel(const float* __restrict__ z,
                    const float* __restrict__ bvec,
                    const float* __restrict__ pattern_emb,
                    const int* __restrict__ pid,
                    float* __restrict__ out) {
    int warp = threadIdx.x >> 5;
    int lane = threadIdx.x & 31;
    int node = blockIdx.x * 16 + warp * 2 + (lane >> 4);
    int sl   = lane & 15;

    float4 acc = agg_node4(z, node, sl);
    float4 b4 = *(const float4*)&bvec[sl * 4];
    acc.x = fmaxf(acc.x + b4.x, 0.f);
    acc.y = fmaxf(acc.y + b4.y, 0.f);
    acc.z = fmaxf(acc.z + b4.z, 0.f);
    acc.w = fmaxf(acc.w + b4.w, 0.f);

    int p_id = __ldg(pid);
    float4 pv = *(const float4*)&pattern_emb[p_id * D + sl * 4];

    float num = acc.x * pv.x + acc.y * pv.y + acc.z * pv.z + acc.w * pv.w;
    float sq  = acc.x * acc.x + acc.y * acc.y + acc.z * acc.z + acc.w * acc.w;
    float psq = pv.x * pv.x + pv.y * pv.y + pv.z * pv.z + pv.w * pv.w;

    #pragma unroll
    for (int o = 8; o > 0; o >>= 1) {   // reduce within 16-lane half
        num += __shfl_xor_sync(0xFFFFFFFFu, num, o);
        sq  += __shfl_xor_sync(0xFFFFFFFFu, sq, o);
        psq += __shfl_xor_sync(0xFFFFFFFFu, psq, o);
    }
    if (sl == 0) {
        float denom = fmaxf(sqrtf(sq), EPS) * fmaxf(sqrtf(psq), EPS);
        out[node] = num / denom;
    }
}

// ---------------- launch ----------------
extern "C" void kernel_launch(void* const* d_in, const int* in_sizes, int n_in,
                              void* d_out, int out_size) {
    const int*   nodes       = (const int*)d_in[0];
    const int2*  edges       = (const int2*)d_in[1];
    const float* features    = (const float*)d_in[2];
    const float* node_emb    = (const float*)d_in[3];
    const float* feat_W      = (const float*)d_in[4];
    const float* feat_b      = (const float*)d_in[5];
    const float* conv1_W     = (const float*)d_in[6];
    const float* conv1_b     = (const float*)d_in[7];
    const float* pattern_emb = (const float*)d_in[8];
    const int*   pattern_id  = (const int*)d_in[9];
    float*       out         = (float*)d_out;

    float* z; float* h; float* z2;
    cudaGetSymbolAddress((void**)&z,  g_z);
    cudaGetSymbolAddress((void**)&h,  g_h);
    cudaGetSymbolAddress((void**)&z2, g_z2);

    // 1: CSR build + folded weights + z1 (persistent)
    csr_build_kernel<<<NB, BT>>>(edges, node_emb, feat_W, feat_b, conv1_W,
                                 nodes, features);
    // 2: layer-1 agg + relu
    agg_relu_kernel<<<N_NODES / 16, 256>>>(z, h, conv1_b);
    // 3: layer-2 linear
    gemm_kernel<<<GEMM_GRID, 128>>>(h, z2, conv1_W);
    // 4: layer-2 agg + relu + cosine
    agg_cos_kernel<<<N_NODES / 16, 256>>>(z2, conv1_b, pattern_emb, pattern_id, out);
}

// round 15
// speedup vs baseline: 1.1611x; 1.1109x over previous
#include <cuda_runtime.h>
#include <cuda_bf16.h>
#include <math.h>

#define N_NODES 100000
#define N_EDGES 800000
#define D 64
#define D_FEAT 10
#define VOCAB 100
#define EPS 1e-8f

#define NB 148     // persistent blocks
#define BT 256
#define CHUNK 676  // ceil(N_NODES / NB)

// packed fp32x2 ops (sm_100+; ptxas only emits via explicit PTX)
#define FMA_F32X2(out, a, b, c) \
    asm("fma.rn.f32x2 %0, %1, %2, %3;" : "=l"(out) : "l"(a), "l"(b), "l"(c))
#define ADD_F32X2(out, a, b) \
    asm("add.rn.f32x2 %0, %1, %2;" : "=l"(out) : "l"(a), "l"(b))

// ---------------- static device scratch ----------------
__device__ float g_z[N_NODES * D];
__device__ float g_h[N_NODES * D];
__device__ float g_z2[N_NODES * D];
__device__ int   g_indeg[N_NODES];
__device__ int   g_off[N_NODES + 1];
__device__ int   g_cursor[N_NODES];
__device__ int   g_srcs[N_EDGES];      // stores BYTE offsets (src * 256)
__device__ float g_nv[VOCAB * D];
__device__ float g_fw2t[D_FEAT * D];   // [k][d]
__device__ float g_c[D];
__device__ unsigned int g_barrier[8];  // zero-init; atomicInc wraps to 0 each replay
__device__ int g_bsum[NB];
__device__ int g_bbase[NB];

// ---------------- grid barrier (self-resetting) ----------------
__device__ __forceinline__ void gbar(int i) {
    __syncthreads();
    if (threadIdx.x == 0) {
        __threadfence();
        atomicInc(&g_barrier[i], NB - 1u);
        volatile unsigned int* p = &g_barrier[i];
        while (*p != 0u) __nanosleep(32);
        __threadfence();
    }
    __syncthreads();
}

// ---------------- K1: zero indeg + folded weights, spread over all blocks ----------------
// 7104 outputs = fw2t(640) + c(64) + nv(6400); 148 blocks x 48 outputs each.
#define WP 65
__global__ __launch_bounds__(BT)
void init_pre_kernel(const float* __restrict__ node_emb,
                     const float* __restrict__ feat_W,
                     const float* __restrict__ feat_b,
                     const float* __restrict__ W) {
    __shared__ float sW[D * WP];
    __shared__ float sFW[D * D_FEAT];
    __shared__ float sFB[D];
    int tid = threadIdx.x;
    int b   = blockIdx.x;
    int gt  = b * BT + tid;

    // zero indeg (coalesced, all blocks)
    for (int i = gt; i < N_NODES; i += NB * BT) g_indeg[i] = 0;

    // stage W coalesced
    for (int i = tid; i < D * D; i += BT) sW[(i >> 6) * WP + (i & 63)] = W[i];
    int obase = b * 48;
    if (obase < 704) {   // this block touches fw2t / c outputs
        for (int i = tid; i < D * D_FEAT; i += BT) sFW[i] = feat_W[i];
        if (tid < D) sFB[tid] = feat_b[tid];
    }
    __syncthreads();

    int warp = tid >> 5, lane = tid & 31;
    for (int t = warp; t < 48; t += 8) {
        int o = obase + t;
        float op0, op1;
        int d;
        if (o < 640) {                       // fw2t[k*D+d] = sum_j W[d][j]*feat_W[j][k]
            int k = o / D; d = o % D;
            op0 = sFW[lane * D_FEAT + k];
            op1 = sFW[(lane + 32) * D_FEAT + k];
        } else if (o < 704) {                // c[d] = sum_j W[d][j]*feat_b[j]
            d = o - 640;
            op0 = sFB[lane];
            op1 = sFB[lane + 32];
        } else {                             // nv[v*D+d] = sum_j node_emb[v][j]*W[d][j]
            int idx = o - 704;
            int v = idx >> 6; d = idx & 63;
            op0 = __ldg(&node_emb[v * D + lane]);
            op1 = __ldg(&node_emb[v * D + lane + 32]);
        }
        float s = sW[d * WP + lane] * op0 + sW[d * WP + lane + 32] * op1;
        #pragma unroll
        for (int off = 16; off; off >>= 1) s += __shfl_xor_sync(0xFFFFFFFFu, s, off);
        if (lane == 0) {
            if (o < 640)      g_fw2t[o] = s;
            else if (o < 704) g_c[o - 640] = s;
            else              g_nv[o - 704] = s;
        }
    }
}

// ---------------- K2: z1 = nv[nodes] + features @ fw2^T + c ----------------
__global__ __launch_bounds__(256)
void z1_kernel(const int* __restrict__ nodes, const float* __restrict__ features) {
    __shared__ float s_fw2t[D_FEAT * D];
    __shared__ float s_c[D];
    int tid = threadIdx.x;
    for (int i = tid; i < D_FEAT * D; i += 256) s_fw2t[i] = g_fw2t[i];
    if (tid < D) s_c[tid] = g_c[tid];
    __syncthreads();

    int q    = blockIdx.x * 256 + tid;
    int node = q >> 4;
    int dq   = (q & 15) * 4;

    int tok = __ldg(&nodes[node]);
    const float* f = features + node * D_FEAT;
    float fk[D_FEAT];
    #pragma unroll
    for (int k = 0; k < D_FEAT; k++) fk[k] = f[k];

    float4 acc = *(const float4*)&g_nv[tok * D + dq];
    float4 cc  = *(const float4*)&s_c[dq];
    acc.x += cc.x; acc.y += cc.y; acc.z += cc.z; acc.w += cc.w;

    #pragma unroll
    for (int k = 0; k < D_FEAT; k++) {
        float4 w4 = *(const float4*)&s_fw2t[k * D + dq];
        acc.x += fk[k] * w4.x; acc.y += fk[k] * w4.y;
        acc.z += fk[k] * w4.z; acc.w += fk[k] * w4.w;
    }
    *(float4*)&g_z[node * D + dq] = acc;
}

// ---------------- K3: count (2 edges per LDG.128) ----------------
__global__ __launch_bounds__(256)
void count_kernel(const int2* __restrict__ edges) {
    int i = blockIdx.x * 256 + threadIdx.x;
    if (i < N_EDGES / 2) {
        int4 p = __ldg(&((const int4*)edges)[i]);
        atomicAdd(&g_indeg[p.y], 1);
        atomicAdd(&g_indeg[p.w], 1);
    }
}

// ---------------- K4: scan (2-level, deterministic) + place ----------------
__global__ __launch_bounds__(BT)
void csr_scan_place_kernel(const int2* __restrict__ edges) {
    int tid  = threadIdx.x;
    int b    = blockIdx.x;
    int lane = tid & 31;
    int w    = tid >> 5;
    int gt   = b * BT + tid;
    const int gs = NB * BT;

    __shared__ int sm8[8];
    int cs = b * CHUNK;
    int ce = min(cs + CHUNK, N_NODES);

    // A: per-block chunk sums
    {
        int s = 0;
        for (int i = cs + tid; i < ce; i += BT) s += g_indeg[i];
        #pragma unroll
        for (int o = 16; o; o >>= 1) s += __shfl_xor_sync(0xFFFFFFFFu, s, o);
        if (lane == 0) sm8[w] = s;
        __syncthreads();
        if (tid == 0) {
            int t = 0;
            #pragma unroll
            for (int k = 0; k < 8; k++) t += sm8[k];
            g_bsum[b] = t;
        }
    }
    gbar(0);

    // B: block 0 scans the 148 block sums (deterministic, globally monotone)
    if (b == 0) {
        int x = (tid < NB) ? g_bsum[tid] : 0;
        int incl = x;
        #pragma unroll
        for (int o = 1; o < 32; o <<= 1) {
            int n = __shfl_up_sync(0xFFFFFFFFu, incl, o);
            if (lane >= o) incl += n;
        }
        __syncthreads();
        if (lane == 31) sm8[w] = incl;
        __syncthreads();
        if (w == 0 && lane < 8) {
            int v = sm8[lane];
            #pragma unroll
            for (int o = 1; o < 8; o <<= 1) {
                int n = __shfl_up_sync(0xFFu, v, o);
                if (lane >= o) v += n;
            }
            sm8[lane] = v;
        }
        __syncthreads();
        int excl = incl - x + (w ? sm8[w - 1] : 0);
        if (tid < NB) g_bbase[tid] = excl;
    }
    gbar(1);

    // C: per-block tile scans -> off, cursor
    {
        int run = g_bbase[b];
        for (int t0 = cs; t0 < cs + CHUNK; t0 += BT) {
            int i = t0 + tid;
            int x = (i < ce) ? g_indeg[i] : 0;
            int incl = x;
            #pragma unroll
            for (int o = 1; o < 32; o <<= 1) {
                int n = __shfl_up_sync(0xFFFFFFFFu, incl, o);
                if (lane >= o) incl += n;
            }
            __syncthreads();
            if (lane == 31) sm8[w] = incl;
            __syncthreads();
            if (w == 0 && lane < 8) {
                int v = sm8[lane];
                #pragma unroll
                for (int o = 1; o < 8; o <<= 1) {
                    int n = __shfl_up_sync(0xFFu, v, o);
                    if (lane >= o) v += n;
                }
                sm8[lane] = v;
            }
            __syncthreads();
            int excl = incl - x + (w ? sm8[w - 1] : 0) + run;
            if (i < ce) { g_off[i] = excl; g_cursor[i] = excl; }
            run += sm8[7];
        }
        if (b == 0 && tid == 0) g_off[N_NODES] = N_EDGES;
    }
    gbar(2);

    // D: place (2 edges per LDG.128); store BYTE offsets (src * 256)
    {
        const int4* e4 = (const int4*)edges;
        for (int i = gt; i < N_EDGES / 2; i += gs) {
            int4 p = __ldg(&e4[i]);
            g_srcs[atomicAdd(&g_cursor[p.y], 1)] = p.x << 8;
            g_srcs[atomicAdd(&g_cursor[p.w], 1)] = p.z << 8;
        }
    }
}

// ---------------- aggregation: half-warp per node, predicated MLP-8, byte offsets ----------------
__device__ __forceinline__ float4 agg_node4(const float* __restrict__ z,
                                            int node, int sl) {
    const char* zb = (const char*)z + sl * 16;     // per-lane base
    ulonglong2 a0 = *(const ulonglong2*)(zb + node * 256);
    unsigned long long e0 = a0.x, e1 = a0.y, o0 = 0ULL, o1 = 0ULL;
    int s0 = __ldg(&g_off[node]);
    int s1 = __ldg(&g_off[node + 1]);

    for (int j = s0; j < s1; j += 8) {
        ulonglong2 v[8];
        #pragma unroll
        for (int k = 0; k < 8; k++) {
            if (j + k < s1) {
                int a = __ldg(&g_srcs[j + k]);   // byte offset; uniform in half-warp
                v[k] = *(const ulonglong2*)(zb + a);
            } else {
                v[k].x = 0ULL; v[k].y = 0ULL;
            }
        }
        #pragma unroll
        for (int k = 0; k < 8; k += 2) {
            ADD_F32X2(e0, e0, v[k].x);     ADD_F32X2(e1, e1, v[k].y);
            ADD_F32X2(o0, o0, v[k + 1].x); ADD_F32X2(o1, o1, v[k + 1].y);
        }
    }
    ADD_F32X2(e0, e0, o0);
    ADD_F32X2(e1, e1, o1);
    float4 r;
    asm("mov.b64 {%0, %1}, %2;" : "=f"(r.x), "=f"(r.y) : "l"(e0));
    asm("mov.b64 {%0, %1}, %2;" : "=f"(r.z), "=f"(r.w) : "l"(e1));
    return r;
}

// ---------------- K5: agg + bias + relu ----------------
__global__ __launch_bounds__(256)
void agg_relu_kernel(const float* __restrict__ z, float* __restrict__ h,
                     const float* __restrict__ bvec) {
    int warp = threadIdx.x >> 5;
    int lane = threadIdx.x & 31;
    int node = blockIdx.x * 16 + warp * 2 + (lane >> 4);
    int sl   = lane & 15;

    float4 acc = agg_node4(z, node, sl);
    float4 b4 = *(const float4*)&bvec[sl * 4];
    acc.x = fmaxf(acc.x + b4.x, 0.f);
    acc.y = fmaxf(acc.y + b4.y, 0.f);
    acc.z = fmaxf(acc.z + b4.z, 0.f);
    acc.w = fmaxf(acc.w + b4.w, 0.f);
    *(float4*)&h[node * D + sl * 4] = acc;
}

// ---------------- K6: GEMM z2 = h @ W^T (2 t-dims per thread, split-K) ----------------
#define GEMM_GRID 592
#define G_TILES (N_NODES / 8)   // 12500 tiles of 8 nodes
__global__ __launch_bounds__(128, 4)
void gemm_kernel(const float* __restrict__ in, float* __restrict__ out,
                 const float* __restrict__ W) {
    __shared__ __align__(16) float xs[8][D];
    __shared__ float ps[8][D];
    int tid = threadIdx.x;
    int t2  = tid & 31;          // output dims t2 and t2+32
    int kh  = (tid >> 5) & 1;    // K half
    int nh  = tid >> 6;          // node half (4 nodes each)

    unsigned long long wa[16], wb[16];
    const unsigned long long* Wa = (const unsigned long long*)(W + t2 * D + kh * 32);
    const unsigned long long* Wb = (const unsigned long long*)(W + (t2 + 32) * D + kh * 32);
    #pragma unroll
    for (int k = 0; k < 16; k++) { wa[k] = Wa[k]; wb[k] = Wb[k]; }

    const float4* src = (const float4*)in;
    int tile = blockIdx.x;
    float4 r0;
    if (tile < G_TILES) r0 = src[tile * 128 + tid];

    for (; tile < G_TILES; tile += GEMM_GRID) {
        ((float4*)xs)[tid] = r0;
        __syncthreads();
        int nt = tile + GEMM_GRID;
        if (nt < G_TILES) r0 = src[nt * 128 + tid];   // prefetch next tile

        unsigned long long acca[4], accb[4];
        #pragma unroll
        for (int n = 0; n < 4; n++) { acca[n] = 0ULL; accb[n] = 0ULL; }

        #pragma unroll
        for (int n = 0; n < 4; n++) {
            const ulonglong2* x = (const ulonglong2*)&xs[nh * 4 + n][kh * 32];
            #pragma unroll
            for (int dp = 0; dp < 8; dp++) {
                ulonglong2 xv = x[dp];                // LDS.128 -> 4 FFMA2
                FMA_F32X2(acca[n], xv.x, wa[2 * dp],     acca[n]);
                FMA_F32X2(accb[n], xv.x, wb[2 * dp],     accb[n]);
                FMA_F32X2(acca[n], xv.y, wa[2 * dp + 1], acca[n]);
                FMA_F32X2(accb[n], xv.y, wb[2 * dp + 1], accb[n]);
            }
        }

        float va[4], vb[4];
        #pragma unroll
        for (int n = 0; n < 4; n++) {
            float lo, hi;
            asm("mov.b64 {%0, %1}, %2;" : "=f"(lo), "=f"(hi) : "l"(acca[n]));
            va[n] = lo + hi;
            asm("mov.b64 {%0, %1}, %2;" : "=f"(lo), "=f"(hi) : "l"(accb[n]));
            vb[n] = lo + hi;
        }

        if (kh == 1) {
            #pragma unroll
            for (int n = 0; n < 4; n++) {
                ps[nh * 4 + n][t2]      = va[n];
                ps[nh * 4 + n][t2 + 32] = vb[n];
            }
        }
        __syncthreads();
        if (kh == 0) {
            int nb = tile * 8 + nh * 4;
            #pragma unroll
            for (int n = 0; n < 4; n++) {
                out[(nb + n) * D + t2]      = va[n] + ps[nh * 4 + n][t2];
                out[(nb + n) * D + t2 + 32] = vb[n] + ps[nh * 4 + n][t2 + 32];
            }
        }
        __syncthreads();
    }
}

// ---------------- K7: fused final agg + bias + relu + cosine ----------------
__global__ __launch_bounds__(256)
void agg_cos_kernel(const float* __restrict__ z,
                    const float* __restrict__ bvec,
                    const float* __restrict__ pattern_emb,
                    const int* __restrict__ pid,
                    float* __restrict__ out) {
    int warp = threadIdx.x >> 5;
    int lane = threadIdx.x & 31;
    int node = blockIdx.x * 16 + warp * 2 + (lane >> 4);
    int sl   = lane & 15;

    float4 acc = agg_node4(z, node, sl);
    float4 b4 = *(const float4*)&bvec[sl * 4];
    acc.x = fmaxf(acc.x + b4.x, 0.f);
    acc.y = fmaxf(acc.y + b4.y, 0.f);
    acc.z = fmaxf(acc.z + b4.z, 0.f);
    acc.w = fmaxf(acc.w + b4.w, 0.f);

    int p_id = __ldg(pid);
    float4 pv = *(const float4*)&pattern_emb[p_id * D + sl * 4];

    float num = acc.x * pv.x + acc.y * pv.y + acc.z * pv.z + acc.w * pv.w;
    float sq  = acc.x * acc.x + acc.y * acc.y + acc.z * acc.z + acc.w * acc.w;
    float psq = pv.x * pv.x + pv.y * pv.y + pv.z * pv.z + pv.w * pv.w;

    #pragma unroll
    for (int o = 8; o > 0; o >>= 1) {   // reduce within 16-lane half
        num += __shfl_xor_sync(0xFFFFFFFFu, num, o);
        sq  += __shfl_xor_sync(0xFFFFFFFFu, sq, o);
        psq += __shfl_xor_sync(0xFFFFFFFFu, psq, o);
    }
    if (sl == 0) {
        float denom = fmaxf(sqrtf(sq), EPS) * fmaxf(sqrtf(psq), EPS);
        out[node] = num / denom;
    }
}

// ---------------- launch ----------------
extern "C" void kernel_launch(void* const* d_in, const int* in_sizes, int n_in,
                              void* d_out, int out_size) {
    const int*   nodes       = (const int*)d_in[0];
    const int2*  edges       = (const int2*)d_in[1];
    const float* features    = (const float*)d_in[2];
    const float* node_emb    = (const float*)d_in[3];
    const float* feat_W      = (const float*)d_in[4];
    const float* feat_b      = (const float*)d_in[5];
    const float* conv1_W     = (const float*)d_in[6];
    const float* conv1_b     = (const float*)d_in[7];
    const float* pattern_emb = (const float*)d_in[8];
    const int*   pattern_id  = (const int*)d_in[9];
    float*       out         = (float*)d_out;

    float* z; float* h; float* z2;
    cudaGetSymbolAddress((void**)&z,  g_z);
    cudaGetSymbolAddress((void**)&h,  g_h);
    cudaGetSymbolAddress((void**)&z2, g_z2);

    // K1: zero indeg + folded weights (spread over 148 blocks)
    init_pre_kernel<<<NB, BT>>>(node_emb, feat_W, feat_b, conv1_W);
    // K2: z1
    z1_kernel<<<(N_NODES * 16) / 256, 256>>>(nodes, features);
    // K3: count
    count_kernel<<<(N_EDGES / 2 + 255) / 256, 256>>>(edges);
    // K4: scan + place (profiled next round)
    csr_scan_place_kernel<<<NB, BT>>>(edges);
    // K5: layer-1 agg + relu
    agg_relu_kernel<<<N_NODES / 16, 256>>>(z, h, conv1_b);
    // K6: layer-2 linear
    gemm_kernel<<<GEMM_GRID, 128>>>(h, z2, conv1_W);
    // K7: layer-2 agg + relu + cosine
    agg_cos_kernel<<<N_NODES / 16, 256>>>(z2, conv1_b, pattern_emb, pattern_id, out);
}

// round 16
// speedup vs baseline: 1.2030x; 1.0361x over previous
#include <cuda_runtime.h>
#include <cuda_bf16.h>
#include <math.h>

#define N_NODES 100000
#define N_EDGES 800000
#define D 64
#define D_FEAT 10
#define VOCAB 100
#define EPS 1e-8f

#define NB 148     // persistent scan blocks
#define BT 256
#define CHUNK 676  // ceil(N_NODES / NB)

#define Z1_BLOCKS ((N_NODES * 16) / 256)          // 6250
#define CNT_BLOCKS ((N_EDGES / 2 + 255) / 256)    // 1563

// packed fp32x2 ops (sm_100+; ptxas only emits via explicit PTX)
#define FMA_F32X2(out, a, b, c) \
    asm("fma.rn.f32x2 %0, %1, %2, %3;" : "=l"(out) : "l"(a), "l"(b), "l"(c))
#define ADD_F32X2(out, a, b) \
    asm("add.rn.f32x2 %0, %1, %2;" : "=l"(out) : "l"(a), "l"(b))

// ---------------- static device scratch ----------------
__device__ float g_z[N_NODES * D];
__device__ float g_h[N_NODES * D];
__device__ float g_z2[N_NODES * D];
__device__ int   g_indeg[N_NODES];
__device__ int   g_off[N_NODES + 1];
__device__ int   g_cursor[N_NODES];
__device__ int   g_srcs[N_EDGES];      // stores BYTE offsets (src * 256)
__device__ float g_nv[VOCAB * D];
__device__ float g_fw2t[D_FEAT * D];   // [k][d]
__device__ float g_c[D];
__device__ unsigned int g_barrier[8];  // zero-init; atomicInc wraps to 0 each replay
__device__ int g_bsum[NB];
__device__ int g_bbase[NB];

// ---------------- grid barrier (self-resetting) ----------------
__device__ __forceinline__ void gbar(int i) {
    __syncthreads();
    if (threadIdx.x == 0) {
        __threadfence();
        atomicInc(&g_barrier[i], NB - 1u);
        volatile unsigned int* p = &g_barrier[i];
        while (*p != 0u) __nanosleep(32);
        __threadfence();
    }
    __syncthreads();
}

// ---------------- K1: zero indeg + folded weights, spread over all blocks ----------------
// 7104 outputs = fw2t(640) + c(64) + nv(6400); 148 blocks x 48 outputs each.
#define WP 65
__global__ __launch_bounds__(BT)
void init_pre_kernel(const float* __restrict__ node_emb,
                     const float* __restrict__ feat_W,
                     const float* __restrict__ feat_b,
                     const float* __restrict__ W) {
    __shared__ float sW[D * WP];
    __shared__ float sFW[D * D_FEAT];
    __shared__ float sFB[D];
    int tid = threadIdx.x;
    int b   = blockIdx.x;
    int gt  = b * BT + tid;

    // zero indeg (coalesced, all blocks)
    for (int i = gt; i < N_NODES; i += NB * BT) g_indeg[i] = 0;

    // stage W coalesced
    for (int i = tid; i < D * D; i += BT) sW[(i >> 6) * WP + (i & 63)] = W[i];
    int obase = b * 48;
    if (obase < 704) {   // this block touches fw2t / c outputs
        for (int i = tid; i < D * D_FEAT; i += BT) sFW[i] = feat_W[i];
        if (tid < D) sFB[tid] = feat_b[tid];
    }
    __syncthreads();

    int warp = tid >> 5, lane = tid & 31;
    for (int t = warp; t < 48; t += 8) {
        int o = obase + t;
        float op0, op1;
        int d;
        if (o < 640) {                       // fw2t[k*D+d] = sum_j W[d][j]*feat_W[j][k]
            int k = o / D; d = o % D;
            op0 = sFW[lane * D_FEAT + k];
            op1 = sFW[(lane + 32) * D_FEAT + k];
        } else if (o < 704) {                // c[d] = sum_j W[d][j]*feat_b[j]
            d = o - 640;
            op0 = sFB[lane];
            op1 = sFB[lane + 32];
        } else {                             // nv[v*D+d] = sum_j node_emb[v][j]*W[d][j]
            int idx = o - 704;
            int v = idx >> 6; d = idx & 63;
            op0 = __ldg(&node_emb[v * D + lane]);
            op1 = __ldg(&node_emb[v * D + lane + 32]);
        }
        float s = sW[d * WP + lane] * op0 + sW[d * WP + lane + 32] * op1;
        #pragma unroll
        for (int off = 16; off; off >>= 1) s += __shfl_xor_sync(0xFFFFFFFFu, s, off);
        if (lane == 0) {
            if (o < 640)      g_fw2t[o] = s;
            else if (o < 704) g_c[o - 640] = s;
            else              g_nv[o - 704] = s;
        }
    }
}

// ---------------- K2: z1 + count, heterogeneous blocks (overlapped pipes) ----------------
__global__ __launch_bounds__(256)
void z1_count_kernel(const int* __restrict__ nodes,
                     const float* __restrict__ features,
                     const int2* __restrict__ edges) {
    int tid = threadIdx.x;
    if (blockIdx.x < Z1_BLOCKS) {
        // z1 = nv[nodes] + features @ fw2^T + c
        __shared__ float s_fw2t[D_FEAT * D];
        __shared__ float s_c[D];
        for (int i = tid; i < D_FEAT * D; i += 256) s_fw2t[i] = g_fw2t[i];
        if (tid < D) s_c[tid] = g_c[tid];
        __syncthreads();

        int q    = blockIdx.x * 256 + tid;
        int node = q >> 4;
        int dq   = (q & 15) * 4;

        int tok = __ldg(&nodes[node]);
        const float* f = features + node * D_FEAT;
        float fk[D_FEAT];
        #pragma unroll
        for (int k = 0; k < D_FEAT; k++) fk[k] = f[k];

        float4 acc = *(const float4*)&g_nv[tok * D + dq];
        float4 cc  = *(const float4*)&s_c[dq];
        acc.x += cc.x; acc.y += cc.y; acc.z += cc.z; acc.w += cc.w;

        #pragma unroll
        for (int k = 0; k < D_FEAT; k++) {
            float4 w4 = *(const float4*)&s_fw2t[k * D + dq];
            acc.x += fk[k] * w4.x; acc.y += fk[k] * w4.y;
            acc.z += fk[k] * w4.z; acc.w += fk[k] * w4.w;
        }
        *(float4*)&g_z[node * D + dq] = acc;
    } else {
        // count (2 edges per LDG.128)
        int i = (blockIdx.x - Z1_BLOCKS) * 256 + tid;
        if (i < N_EDGES / 2) {
            int4 p = __ldg(&((const int4*)edges)[i]);
            atomicAdd(&g_indeg[p.y], 1);
            atomicAdd(&g_indeg[p.w], 1);
        }
    }
}

// ---------------- K3: scan (2-level, deterministic), 148 persistent blocks ----------------
__global__ __launch_bounds__(BT)
void scan_kernel() {
    int tid  = threadIdx.x;
    int b    = blockIdx.x;
    int lane = tid & 31;
    int w    = tid >> 5;

    __shared__ int sm8[8];
    int cs = b * CHUNK;
    int ce = min(cs + CHUNK, N_NODES);

    // A: per-block chunk sums
    {
        int s = 0;
        for (int i = cs + tid; i < ce; i += BT) s += g_indeg[i];
        #pragma unroll
        for (int o = 16; o; o >>= 1) s += __shfl_xor_sync(0xFFFFFFFFu, s, o);
        if (lane == 0) sm8[w] = s;
        __syncthreads();
        if (tid == 0) {
            int t = 0;
            #pragma unroll
            for (int k = 0; k < 8; k++) t += sm8[k];
            g_bsum[b] = t;
        }
    }
    gbar(0);

    // B: block 0 scans the 148 block sums (deterministic, globally monotone)
    if (b == 0) {
        int x = (tid < NB) ? g_bsum[tid] : 0;
        int incl = x;
        #pragma unroll
        for (int o = 1; o < 32; o <<= 1) {
            int n = __shfl_up_sync(0xFFFFFFFFu, incl, o);
            if (lane >= o) incl += n;
        }
        __syncthreads();
        if (lane == 31) sm8[w] = incl;
        __syncthreads();
        if (w == 0 && lane < 8) {
            int v = sm8[lane];
            #pragma unroll
            for (int o = 1; o < 8; o <<= 1) {
                int n = __shfl_up_sync(0xFFu, v, o);
                if (lane >= o) v += n;
            }
            sm8[lane] = v;
        }
        __syncthreads();
        int excl = incl - x + (w ? sm8[w - 1] : 0);
        if (tid < NB) g_bbase[tid] = excl;
    }
    gbar(1);

    // C: per-block tile scans -> off, cursor (kernel boundary syncs before place)
    {
        int run = g_bbase[b];
        for (int t0 = cs; t0 < cs + CHUNK; t0 += BT) {
            int i = t0 + tid;
            int x = (i < ce) ? g_indeg[i] : 0;
            int incl = x;
            #pragma unroll
            for (int o = 1; o < 32; o <<= 1) {
                int n = __shfl_up_sync(0xFFFFFFFFu, incl, o);
                if (lane >= o) incl += n;
            }
            __syncthreads();
            if (lane == 31) sm8[w] = incl;
            __syncthreads();
            if (w == 0 && lane < 8) {
                int v = sm8[lane];
                #pragma unroll
                for (int o = 1; o < 8; o <<= 1) {
                    int n = __shfl_up_sync(0xFFu, v, o);
                    if (lane >= o) v += n;
                }
                sm8[lane] = v;
            }
            __syncthreads();
            int excl = incl - x + (w ? sm8[w - 1] : 0) + run;
            if (i < ce) { g_off[i] = excl; g_cursor[i] = excl; }
            run += sm8[7];
        }
        if (b == 0 && tid == 0) g_off[N_NODES] = N_EDGES;
    }
}

// ---------------- K4: place, wide grid (latency hidden by thread count) ----------------
__global__ __launch_bounds__(256)
void place_kernel(const int2* __restrict__ edges) {
    int i = blockIdx.x * 256 + threadIdx.x;
    if (i < N_EDGES / 2) {
        int4 p = __ldg(&((const int4*)edges)[i]);
        g_srcs[atomicAdd(&g_cursor[p.y], 1)] = p.x << 8;   // byte offsets
        g_srcs[atomicAdd(&g_cursor[p.w], 1)] = p.z << 8;
    }
}

// ---------------- aggregation: half-warp per node, predicated MLP-8, byte offsets ----------------
__device__ __forceinline__ float4 agg_node4(const float* __restrict__ z,
                                            int node, int sl) {
    const char* zb = (const char*)z + sl * 16;     // per-lane base
    ulonglong2 a0 = *(const ulonglong2*)(zb + node * 256);
    unsigned long long e0 = a0.x, e1 = a0.y, o0 = 0ULL, o1 = 0ULL;
    int s0 = __ldg(&g_off[node]);
    int s1 = __ldg(&g_off[node + 1]);

    for (int j = s0; j < s1; j += 8) {
        ulonglong2 v[8];
        #pragma unroll
        for (int k = 0; k < 8; k++) {
            if (j + k < s1) {
                int a = __ldg(&g_srcs[j + k]);   // byte offset; uniform in half-warp
                v[k] = *(const ulonglong2*)(zb + a);
            } else {
                v[k].x = 0ULL; v[k].y = 0ULL;
            }
        }
        #pragma unroll
        for (int k = 0; k < 8; k += 2) {
            ADD_F32X2(e0, e0, v[k].x);     ADD_F32X2(e1, e1, v[k].y);
            ADD_F32X2(o0, o0, v[k + 1].x); ADD_F32X2(o1, o1, v[k + 1].y);
        }
    }
    ADD_F32X2(e0, e0, o0);
    ADD_F32X2(e1, e1, o1);
    float4 r;
    asm("mov.b64 {%0, %1}, %2;" : "=f"(r.x), "=f"(r.y) : "l"(e0));
    asm("mov.b64 {%0, %1}, %2;" : "=f"(r.z), "=f"(r.w) : "l"(e1));
    return r;
}

// ---------------- K5: agg + bias + relu ----------------
__global__ __launch_bounds__(256)
void agg_relu_kernel(const float* __restrict__ z, float* __restrict__ h,
                     const float* __restrict__ bvec) {
    int warp = threadIdx.x >> 5;
    int lane = threadIdx.x & 31;
    int node = blockIdx.x * 16 + warp * 2 + (lane >> 4);
    int sl   = lane & 15;

    float4 acc = agg_node4(z, node, sl);
    float4 b4 = *(const float4*)&bvec[sl * 4];
    acc.x = fmaxf(acc.x + b4.x, 0.f);
    acc.y = fmaxf(acc.y + b4.y, 0.f);
    acc.z = fmaxf(acc.z + b4.z, 0.f);
    acc.w = fmaxf(acc.w + b4.w, 0.f);
    *(float4*)&h[node * D + sl * 4] = acc;
}

// ---------------- K6: GEMM z2 = h @ W^T (2 t-dims per thread, split-K) ----------------
#define GEMM_GRID 592
#define G_TILES (N_NODES / 8)   // 12500 tiles of 8 nodes
__global__ __launch_bounds__(128, 4)
void gemm_kernel(const float* __restrict__ in, float* __restrict__ out,
                 const float* __restrict__ W) {
    __shared__ __align__(16) float xs[8][D];
    __shared__ float ps[8][D];
    int tid = threadIdx.x;
    int t2  = tid & 31;          // output dims t2 and t2+32
    int kh  = (tid >> 5) & 1;    // K half
    int nh  = tid >> 6;          // node half (4 nodes each)

    unsigned long long wa[16], wb[16];
    const unsigned long long* Wa = (const unsigned long long*)(W + t2 * D + kh * 32);
    const unsigned long long* Wb = (const unsigned long long*)(W + (t2 + 32) * D + kh * 32);
    #pragma unroll
    for (int k = 0; k < 16; k++) { wa[k] = Wa[k]; wb[k] = Wb[k]; }

    const float4* src = (const float4*)in;
    int tile = blockIdx.x;
    float4 r0;
    if (tile < G_TILES) r0 = src[tile * 128 + tid];

    for (; tile < G_TILES; tile += GEMM_GRID) {
        ((float4*)xs)[tid] = r0;
        __syncthreads();
        int nt = tile + GEMM_GRID;
        if (nt < G_TILES) r0 = src[nt * 128 + tid];   // prefetch next tile

        unsigned long long acca[4], accb[4];
        #pragma unroll
        for (int n = 0; n < 4; n++) { acca[n] = 0ULL; accb[n] = 0ULL; }

        #pragma unroll
        for (int n = 0; n < 4; n++) {
            const ulonglong2* x = (const ulonglong2*)&xs[nh * 4 + n][kh * 32];
            #pragma unroll
            for (int dp = 0; dp < 8; dp++) {
                ulonglong2 xv = x[dp];                // LDS.128 -> 4 FFMA2
                FMA_F32X2(acca[n], xv.x, wa[2 * dp],     acca[n]);
                FMA_F32X2(accb[n], xv.x, wb[2 * dp],     accb[n]);
                FMA_F32X2(acca[n], xv.y, wa[2 * dp + 1], acca[n]);
                FMA_F32X2(accb[n], xv.y, wb[2 * dp + 1], accb[n]);
            }
        }

        float va[4], vb[4];
        #pragma unroll
        for (int n = 0; n < 4; n++) {
            float lo, hi;
            asm("mov.b64 {%0, %1}, %2;" : "=f"(lo), "=f"(hi) : "l"(acca[n]));
            va[n] = lo + hi;
            asm("mov.b64 {%0, %1}, %2;" : "=f"(lo), "=f"(hi) : "l"(accb[n]));
            vb[n] = lo + hi;
        }

        if (kh == 1) {
            #pragma unroll
            for (int n = 0; n < 4; n++) {
                ps[nh * 4 + n][t2]      = va[n];
                ps[nh * 4 + n][t2 + 32] = vb[n];
            }
        }
        __syncthreads();
        if (kh == 0) {
            int nb = tile * 8 + nh * 4;
            #pragma unroll
            for (int n = 0; n < 4; n++) {
                out[(nb + n) * D + t2]      = va[n] + ps[nh * 4 + n][t2];
                out[(nb + n) * D + t2 + 32] = vb[n] + ps[nh * 4 + n][t2 + 32];
            }
        }
        __syncthreads();
    }
}

// ---------------- K7: fused final agg + bias + relu + cosine ----------------
__global__ __launch_bounds__(256)
void agg_cos_kernel(const float* __restrict__ z,
                    const float* __restrict__ bvec,
                    const float* __restrict__ pattern_emb,
                    const int* __restrict__ pid,
                    float* __restrict__ out) {
    int warp = threadIdx.x >> 5;
    int lane = threadIdx.x & 31;
    int node = blockIdx.x * 16 + warp * 2 + (lane >> 4);
    int sl   = lane & 15;

    float4 acc = agg_node4(z, node, sl);
    float4 b4 = *(const float4*)&bvec[sl * 4];
    acc.x = fmaxf(acc.x + b4.x, 0.f);
    acc.y = fmaxf(acc.y + b4.y, 0.f);
    acc.z = fmaxf(acc.z + b4.z, 0.f);
    acc.w = fmaxf(acc.w + b4.w, 0.f);

    int p_id = __ldg(pid);
    float4 pv = *(const float4*)&pattern_emb[p_id * D + sl * 4];

    float num = acc.x * pv.x + acc.y * pv.y + acc.z * pv.z + acc.w * pv.w;
    float sq  = acc.x * acc.x + acc.y * acc.y + acc.z * acc.z + acc.w * acc.w;
    float psq = pv.x * pv.x + pv.y * pv.y + pv.z * pv.z + pv.w * pv.w;

    #pragma unroll
    for (int o = 8; o > 0; o >>= 1) {   // reduce within 16-lane half
        num += __shfl_xor_sync(0xFFFFFFFFu, num, o);
        sq  += __shfl_xor_sync(0xFFFFFFFFu, sq, o);
        psq += __shfl_xor_sync(0xFFFFFFFFu, psq, o);
    }
    if (sl == 0) {
        float denom = fmaxf(sqrtf(sq), EPS) * fmaxf(sqrtf(psq), EPS);
        out[node] = num / denom;
    }
}

// ---------------- launch ----------------
extern "C" void kernel_launch(void* const* d_in, const int* in_sizes, int n_in,
                              void* d_out, int out_size) {
    const int*   nodes       = (const int*)d_in[0];
    const int2*  edges       = (const int2*)d_in[1];
    const float* features    = (const float*)d_in[2];
    const float* node_emb    = (const float*)d_in[3];
    const float* feat_W      = (const float*)d_in[4];
    const float* feat_b      = (const float*)d_in[5];
    const float* conv1_W     = (const float*)d_in[6];
    const float* conv1_b     = (const float*)d_in[7];
    const float* pattern_emb = (const float*)d_in[8];
    const int*   pattern_id  = (const int*)d_in[9];
    float*       out         = (float*)d_out;

    float* z; float* h; float* z2;
    cudaGetSymbolAddress((void**)&z,  g_z);
    cudaGetSymbolAddress((void**)&h,  g_h);
    cudaGetSymbolAddress((void**)&z2, g_z2);

    // K1: zero indeg + folded weights
    init_pre_kernel<<<NB, BT>>>(node_emb, feat_W, feat_b, conv1_W);
    // K2: z1 + count (heterogeneous blocks, overlapped)
    z1_count_kernel<<<Z1_BLOCKS + CNT_BLOCKS, 256>>>(nodes, features, edges);
    // K3: scan (148 persistent blocks, 2 gbars)
    scan_kernel<<<NB, BT>>>();
    // K4: place (wide grid; profiled next round)
    place_kernel<<<CNT_BLOCKS, 256>>>(edges);
    // K5: layer-1 agg + relu
    agg_relu_kernel<<<N_NODES / 16, 256>>>(z, h, conv1_b);
    // K6: layer-2 linear
    gemm_kernel<<<GEMM_GRID, 128>>>(h, z2, conv1_W);
    // K7: layer-2 agg + relu + cosine
    agg_cos_kernel<<<N_NODES / 16, 256>>>(z2, conv1_b, pattern_emb, pattern_id, out);
}